// round 5
// baseline (speedup 1.0000x reference)
#include <cuda_runtime.h>
#include <math.h>

// Problem constants
#define BATCH   256
#define SEQ     256
#define CQKV    128
#define NHEADS  4
#define CHID    32
#define HC      128   // NHEADS*CHID

// Scratch (allocation-free: __device__ globals)
// q,k: [b][h][s][c]; v: [b][h][c][s] (transposed for the PV GEMM); g,o: [b][s][hc]
static __device__ float g_q[BATCH * NHEADS * SEQ * CHID];
static __device__ float g_k[BATCH * NHEADS * SEQ * CHID];
static __device__ float g_v[BATCH * NHEADS * SEQ * CHID];
static __device__ float g_g[BATCH * SEQ * HC];
static __device__ float g_o[BATCH * SEQ * HC];

// ---------------------------------------------------------------------------
// Kernel 1: fused QKVG projection.  out[m][f] = sum_c in[m][c] * W[f][c]
// M = 65536 (b*s), N = 512, K = 128.  Block tile 64M x 64N, thread 4x4.
// Results scattered into q/k/v/g scratch with attention-friendly layouts.
// ---------------------------------------------------------------------------
#define G1_AS_LD 132   // As[64][132]
#define G1_BS_LD 68    // Bs[128][68]  (Bs[k][f], transposed W)
#define G1_SMEM  ((64 * G1_AS_LD + 128 * G1_BS_LD) * 4)

__global__ __launch_bounds__(256) void gemm_qkvg_kernel(
    const float* __restrict__ in, const float* __restrict__ W)
{
    extern __shared__ float sm[];
    float* As = sm;                  // [64][132]
    float* Bs = sm + 64 * G1_AS_LD;  // [128][68]

    const int t  = threadIdx.x;
    const int m0 = blockIdx.x * 64;
    const int f0 = blockIdx.y * 64;

    // Load A tile [64][128]
#pragma unroll
    for (int i = 0; i < 8; i++) {
        int idx = i * 256 + t;          // float4 index (2048 total)
        int row = idx >> 5, c4 = idx & 31;
        float4 v = *(const float4*)(in + (size_t)(m0 + row) * CQKV + c4 * 4);
        *(float4*)(As + row * G1_AS_LD + c4 * 4) = v;
    }
    // Load B tile transposed: Bs[c][f_local] = W[f0+f_local][c]
#pragma unroll
    for (int i = 0; i < 8; i++) {
        int idx = i * 256 + t;
        int fr = idx >> 5, c4 = idx & 31;
        float4 v = *(const float4*)(W + (size_t)(f0 + fr) * CQKV + c4 * 4);
        Bs[(c4 * 4 + 0) * G1_BS_LD + fr] = v.x;
        Bs[(c4 * 4 + 1) * G1_BS_LD + fr] = v.y;
        Bs[(c4 * 4 + 2) * G1_BS_LD + fr] = v.z;
        Bs[(c4 * 4 + 3) * G1_BS_LD + fr] = v.w;
    }
    __syncthreads();

    const int tx = t & 15, ty = t >> 4;
    float acc[4][4];
#pragma unroll
    for (int i = 0; i < 4; i++)
#pragma unroll
        for (int j = 0; j < 4; j++) acc[i][j] = 0.0f;

#pragma unroll 8
    for (int k = 0; k < 128; k++) {
        float a[4];
#pragma unroll
        for (int i = 0; i < 4; i++) a[i] = As[(ty * 4 + i) * G1_AS_LD + k];
        float4 b4 = *(const float4*)(Bs + k * G1_BS_LD + tx * 4);
#pragma unroll
        for (int i = 0; i < 4; i++) {
            acc[i][0] += a[i] * b4.x;
            acc[i][1] += a[i] * b4.y;
            acc[i][2] += a[i] * b4.z;
            acc[i][3] += a[i] * b4.w;
        }
    }

    // Scatter stores into layout-specific scratch
#pragma unroll
    for (int i = 0; i < 4; i++) {
        int m = m0 + ty * 4 + i;
        int b = m >> 8, s = m & 255;
#pragma unroll
        for (int j = 0; j < 4; j++) {
            int f   = f0 + tx * 4 + j;
            float v = acc[i][j];
            int sec = f >> 7;        // 0:q 1:k 2:v 3:g
            int r   = f & 127;
            int h   = r >> 5, c = r & 31;
            if (sec == 0)      g_q[(((b * NHEADS + h) * SEQ) + s) * CHID + c] = v;
            else if (sec == 1) g_k[(((b * NHEADS + h) * SEQ) + s) * CHID + c] = v;
            else if (sec == 2) g_v[(((b * NHEADS + h) * CHID) + c) * SEQ + s] = v;  // transposed
            else               g_g[(b * SEQ + s) * HC + r] = v;
        }
    }
}

// ---------------------------------------------------------------------------
// Kernel 2: attention per (b, h, q-tile of 64).
//   S = (Q*scale) K^T  (+bias, +(mask-1)*1e9) -> softmax -> O = P V
// smem: Qs[64][33], Ks[256][33], VT[32][260], Ps[64][264]
// ---------------------------------------------------------------------------
#define A_QS_LD 33
#define A_KS_LD 33
#define A_VT_LD 260
#define A_PS_LD 264
#define A_SMEM  ((64 * A_QS_LD + 256 * A_KS_LD + 32 * A_VT_LD + 64 * A_PS_LD) * 4)

__global__ __launch_bounds__(256) void attn_kernel(
    const float* __restrict__ mask, const float* __restrict__ bias)
{
    extern __shared__ float sm[];
    float* Qs = sm;
    float* Ks = Qs + 64 * A_QS_LD;
    float* VT = Ks + 256 * A_KS_LD;
    float* Ps = VT + 32 * A_VT_LD;

    const int t  = threadIdx.x;
    const int q0 = blockIdx.x * 64;
    const int h  = blockIdx.y;
    const int b  = blockIdx.z;
    const float scale = 0.17677669529663687f;  // 1/sqrt(32)

    const size_t bh = (size_t)(b * NHEADS + h);
    const float* qg = g_q + bh * (SEQ * CHID) + (size_t)q0 * CHID;
    const float* kg = g_k + bh * (SEQ * CHID);
    const float* vg = g_v + bh * (SEQ * CHID);   // [c][s]

    // Load Q (scaled), 512 float4
#pragma unroll
    for (int i = 0; i < 2; i++) {
        int idx = i * 256 + t;
        int row = idx >> 3, c4 = idx & 7;
        float4 v = *(const float4*)(qg + row * CHID + c4 * 4);
        float* d = Qs + row * A_QS_LD + c4 * 4;
        d[0] = v.x * scale; d[1] = v.y * scale; d[2] = v.z * scale; d[3] = v.w * scale;
    }
    // Load K, 2048 float4
#pragma unroll
    for (int i = 0; i < 8; i++) {
        int idx = i * 256 + t;
        int row = idx >> 3, c4 = idx & 7;
        float4 v = *(const float4*)(kg + row * CHID + c4 * 4);
        float* d = Ks + row * A_KS_LD + c4 * 4;
        d[0] = v.x; d[1] = v.y; d[2] = v.z; d[3] = v.w;
    }
    // Load V transposed [32][256], 2048 float4 (already transposed in scratch)
#pragma unroll
    for (int i = 0; i < 8; i++) {
        int idx = i * 256 + t;
        int c = idx >> 6, s4 = idx & 63;
        float4 v = *(const float4*)(vg + c * SEQ + s4 * 4);
        *(float4*)(VT + c * A_VT_LD + s4 * 4) = v;
    }
    __syncthreads();

    const int tx = t & 15, ty = t >> 4;

    // Phase 1: scores.  Rows qi = ty*4+i, cols kj = tx + 16*j
    float acc[4][16];
#pragma unroll
    for (int i = 0; i < 4; i++)
#pragma unroll
        for (int j = 0; j < 16; j++) acc[i][j] = 0.0f;

#pragma unroll 4
    for (int d = 0; d < 32; d++) {
        float a[4];
#pragma unroll
        for (int i = 0; i < 4; i++) a[i] = Qs[(ty * 4 + i) * A_QS_LD + d];
#pragma unroll
        for (int j = 0; j < 16; j++) {
            float bk = Ks[(tx + 16 * j) * A_KS_LD + d];
#pragma unroll
            for (int i = 0; i < 4; i++) acc[i][j] += a[i] * bk;
        }
    }

    // mask term (same for all rows of this block)
    float mvals[16];
#pragma unroll
    for (int j = 0; j < 16; j++)
        mvals[j] = (mask[b * SEQ + tx + 16 * j] - 1.0f) * 1e9f;

    const float* bptr = bias + ((size_t)h * SEQ + q0) * SEQ;

    // softmax per row; each row is owned by a 16-lane half-warp (fixed ty)
#pragma unroll
    for (int i = 0; i < 4; i++) {
        const int qi = ty * 4 + i;
        float mx = -3.0e38f;
#pragma unroll
        for (int j = 0; j < 16; j++) {
            float x = acc[i][j] + bptr[qi * SEQ + tx + 16 * j] + mvals[j];
            acc[i][j] = x;
            mx = fmaxf(mx, x);
        }
#pragma unroll
        for (int d = 8; d >= 1; d >>= 1)
            mx = fmaxf(mx, __shfl_xor_sync(0xffffffffu, mx, d, 16));
        float sum = 0.0f;
#pragma unroll
        for (int j = 0; j < 16; j++) {
            float e = __expf(acc[i][j] - mx);
            acc[i][j] = e;
            sum += e;
        }
#pragma unroll
        for (int d = 8; d >= 1; d >>= 1)
            sum += __shfl_xor_sync(0xffffffffu, sum, d, 16);
        float inv = 1.0f / sum;
#pragma unroll
        for (int j = 0; j < 16; j++)
            Ps[qi * A_PS_LD + tx + 16 * j] = acc[i][j] * inv;
    }
    __syncthreads();

    // Phase 2: O[64][32] = P[64][256] @ V.  Thread: 4 rows x 2 channels (tx, tx+16)
    float o0[4] = {0, 0, 0, 0};
    float o1[4] = {0, 0, 0, 0};
#pragma unroll 4
    for (int k4 = 0; k4 < 64; k4++) {
        float4 vb0 = *(const float4*)(VT + tx * A_VT_LD + k4 * 4);
        float4 vb1 = *(const float4*)(VT + (tx + 16) * A_VT_LD + k4 * 4);
#pragma unroll
        for (int i = 0; i < 4; i++) {
            float4 p = *(const float4*)(Ps + (ty * 4 + i) * A_PS_LD + k4 * 4);
            o0[i] += p.x * vb0.x; o0[i] += p.y * vb0.y;
            o0[i] += p.z * vb0.z; o0[i] += p.w * vb0.w;
            o1[i] += p.x * vb1.x; o1[i] += p.y * vb1.y;
            o1[i] += p.z * vb1.z; o1[i] += p.w * vb1.w;
        }
    }
#pragma unroll
    for (int i = 0; i < 4; i++) {
        size_t base = ((size_t)(b * SEQ + q0 + ty * 4 + i)) * HC + h * CHID;
        g_o[base + tx]      = o0[i];
        g_o[base + tx + 16] = o1[i];
    }
}

// ---------------------------------------------------------------------------
// Kernel 3: gate + output projection + transposed add.
//   gated[m][f] = o[m][f] * sigmoid(g[m][f] + gbias[f])
//   proj[m][o]  = sum_f gated[m][f] * Wo[o][f] + bo[o]
//   out[s][b][o] = add[s][b][o] + proj[b*256+s][o]
// Block tile: 64 M x 128 N (full N).  Thread: 4 rows x 8 cols.
// ---------------------------------------------------------------------------
#define G3_AS_LD 132
#define G3_BS_LD 132
#define G3_SMEM  ((64 * G3_AS_LD + 128 * G3_BS_LD) * 4)

__device__ __forceinline__ float sigmoidf_(float x) {
    return 1.0f / (1.0f + __expf(-x));
}

__global__ __launch_bounds__(256) void outproj_kernel(
    const float* __restrict__ addt, const float* __restrict__ gbias,
    const float* __restrict__ Wo,   const float* __restrict__ bo,
    float* __restrict__ out)
{
    extern __shared__ float sm[];
    float* As = sm;                  // gated [64][132]
    float* Bs = sm + 64 * G3_AS_LD;  // WoT   [128][132]  (Bs[f][o])

    const int t  = threadIdx.x;
    const int m0 = blockIdx.x * 64;

    // Load gated A tile
#pragma unroll
    for (int i = 0; i < 8; i++) {
        int idx = i * 256 + t;
        int row = idx >> 5, c4 = idx & 31;
        size_t off = ((size_t)(m0 + row)) * HC + c4 * 4;
        float4 ov = *(const float4*)(g_o + off);
        float4 gv = *(const float4*)(g_g + off);
        float4 gb = *(const float4*)(gbias + c4 * 4);
        float4 r;
        r.x = ov.x * sigmoidf_(gv.x + gb.x);
        r.y = ov.y * sigmoidf_(gv.y + gb.y);
        r.z = ov.z * sigmoidf_(gv.z + gb.z);
        r.w = ov.w * sigmoidf_(gv.w + gb.w);
        *(float4*)(As + row * G3_AS_LD + c4 * 4) = r;
    }
    // Load Wo transposed: Bs[f][o] = Wo[o][f]
#pragma unroll
    for (int i = 0; i < 16; i++) {
        int idx = i * 256 + t;
        int o = idx >> 5, c4 = idx & 31;
        float4 v = *(const float4*)(Wo + (size_t)o * HC + c4 * 4);
        Bs[(c4 * 4 + 0) * G3_BS_LD + o] = v.x;
        Bs[(c4 * 4 + 1) * G3_BS_LD + o] = v.y;
        Bs[(c4 * 4 + 2) * G3_BS_LD + o] = v.z;
        Bs[(c4 * 4 + 3) * G3_BS_LD + o] = v.w;
    }
    __syncthreads();

    const int tx = t & 15, ty = t >> 4;
    float acc[4][8];
#pragma unroll
    for (int i = 0; i < 4; i++)
#pragma unroll
        for (int j = 0; j < 8; j++) acc[i][j] = 0.0f;

#pragma unroll 8
    for (int k = 0; k < 128; k++) {
        float a[4];
#pragma unroll
        for (int i = 0; i < 4; i++) a[i] = As[(ty * 4 + i) * G3_AS_LD + k];
        float4 b0 = *(const float4*)(Bs + k * G3_BS_LD + tx * 4);
        float4 b1 = *(const float4*)(Bs + k * G3_BS_LD + 64 + tx * 4);
#pragma unroll
        for (int i = 0; i < 4; i++) {
            acc[i][0] += a[i] * b0.x; acc[i][1] += a[i] * b0.y;
            acc[i][2] += a[i] * b0.z; acc[i][3] += a[i] * b0.w;
            acc[i][4] += a[i] * b1.x; acc[i][5] += a[i] * b1.y;
            acc[i][6] += a[i] * b1.z; acc[i][7] += a[i] * b1.w;
        }
    }

    float4 bo0 = *(const float4*)(bo + tx * 4);
    float4 bo1 = *(const float4*)(bo + 64 + tx * 4);
#pragma unroll
    for (int i = 0; i < 4; i++) {
        int m = m0 + ty * 4 + i;
        int b = m >> 8, s = m & 255;
        size_t obase = ((size_t)(s * SEQ + b)) * CQKV;  // out[s][b][:]
        float4 a0 = *(const float4*)(addt + obase + tx * 4);
        float4 a1 = *(const float4*)(addt + obase + 64 + tx * 4);
        float4 r0, r1;
        r0.x = acc[i][0] + bo0.x + a0.x; r0.y = acc[i][1] + bo0.y + a0.y;
        r0.z = acc[i][2] + bo0.z + a0.z; r0.w = acc[i][3] + bo0.w + a0.w;
        r1.x = acc[i][4] + bo1.x + a1.x; r1.y = acc[i][5] + bo1.y + a1.y;
        r1.z = acc[i][6] + bo1.z + a1.z; r1.w = acc[i][7] + bo1.w + a1.w;
        *(float4*)(out + obase + tx * 4) = r0;
        *(float4*)(out + obase + 64 + tx * 4) = r1;
    }
}

// ---------------------------------------------------------------------------
extern "C" void kernel_launch(void* const* d_in, const int* in_sizes, int n_in,
                              void* d_out, int out_size)
{
    const float* in_qkv = (const float*)d_in[0];
    const float* mask   = (const float*)d_in[1];
    const float* bias   = (const float*)d_in[2];
    const float* addt   = (const float*)d_in[3];
    const float* Wqkvg  = (const float*)d_in[4];
    const float* gbias  = (const float*)d_in[5];
    const float* Wo     = (const float*)d_in[6];
    const float* bo     = (const float*)d_in[7];
    float* out = (float*)d_out;

    cudaFuncSetAttribute(gemm_qkvg_kernel,
                         cudaFuncAttributeMaxDynamicSharedMemorySize, G1_SMEM);
    cudaFuncSetAttribute(attn_kernel,
                         cudaFuncAttributeMaxDynamicSharedMemorySize, A_SMEM);
    cudaFuncSetAttribute(outproj_kernel,
                         cudaFuncAttributeMaxDynamicSharedMemorySize, G3_SMEM);

    gemm_qkvg_kernel<<<dim3(1024, 8), 256, G1_SMEM>>>(in_qkv, Wqkvg);
    attn_kernel<<<dim3(4, NHEADS, BATCH), 256, A_SMEM>>>(mask, bias);
    outproj_kernel<<<dim3(1024), 256, G3_SMEM>>>(addt, gbias, Wo, bo, out);
}

// round 6
// speedup vs baseline: 1.0557x; 1.0557x over previous
#include <cuda_runtime.h>
#include <math.h>

// Problem constants
#define BATCH   256
#define SEQ     256
#define CQKV    128
#define NHEADS  4
#define CHID    32
#define HC      128   // NHEADS*CHID

// Scratch (allocation-free: __device__ globals)
// q,k: [b][h][s][c]; v: [b][h][c][s] (transposed for the PV GEMM); g,o: [b][s][hc]
static __device__ float g_q[BATCH * NHEADS * SEQ * CHID];
static __device__ float g_k[BATCH * NHEADS * SEQ * CHID];
static __device__ float g_v[BATCH * NHEADS * SEQ * CHID];
static __device__ float g_g[BATCH * SEQ * HC];
static __device__ float g_o[BATCH * SEQ * HC];

// ---------------------------------------------------------------------------
// Kernel 1: fused QKVG projection.  out[m][f] = sum_c in[m][c] * W[f][c]
// M = 65536 (b*s), N = 512, K = 128.  Block tile 64M x 64N, thread 4x4.
// Results scattered into q/k/v/g scratch with attention-friendly layouts.
// ---------------------------------------------------------------------------
#define G1_AS_LD 132   // As[64][132]
#define G1_BS_LD 68    // Bs[128][68]  (Bs[k][f], transposed W)
#define G1_SMEM  ((64 * G1_AS_LD + 128 * G1_BS_LD) * 4)

__global__ __launch_bounds__(256) void gemm_qkvg_kernel(
    const float* __restrict__ in, const float* __restrict__ W)
{
    extern __shared__ float sm[];
    float* As = sm;                  // [64][132]
    float* Bs = sm + 64 * G1_AS_LD;  // [128][68]

    const int t  = threadIdx.x;
    const int m0 = blockIdx.x * 64;
    const int f0 = blockIdx.y * 64;

    // Load A tile [64][128]
#pragma unroll
    for (int i = 0; i < 8; i++) {
        int idx = i * 256 + t;          // float4 index (2048 total)
        int row = idx >> 5, c4 = idx & 31;
        float4 v = *(const float4*)(in + (size_t)(m0 + row) * CQKV + c4 * 4);
        *(float4*)(As + row * G1_AS_LD + c4 * 4) = v;
    }
    // Load B tile transposed: Bs[c][f_local] = W[f0+f_local][c]
#pragma unroll
    for (int i = 0; i < 8; i++) {
        int idx = i * 256 + t;
        int fr = idx >> 5, c4 = idx & 31;
        float4 v = *(const float4*)(W + (size_t)(f0 + fr) * CQKV + c4 * 4);
        Bs[(c4 * 4 + 0) * G1_BS_LD + fr] = v.x;
        Bs[(c4 * 4 + 1) * G1_BS_LD + fr] = v.y;
        Bs[(c4 * 4 + 2) * G1_BS_LD + fr] = v.z;
        Bs[(c4 * 4 + 3) * G1_BS_LD + fr] = v.w;
    }
    __syncthreads();

    const int tx = t & 15, ty = t >> 4;
    float acc[4][4];
#pragma unroll
    for (int i = 0; i < 4; i++)
#pragma unroll
        for (int j = 0; j < 4; j++) acc[i][j] = 0.0f;

#pragma unroll 8
    for (int k = 0; k < 128; k++) {
        float a[4];
#pragma unroll
        for (int i = 0; i < 4; i++) a[i] = As[(ty * 4 + i) * G1_AS_LD + k];
        float4 b4 = *(const float4*)(Bs + k * G1_BS_LD + tx * 4);
#pragma unroll
        for (int i = 0; i < 4; i++) {
            acc[i][0] += a[i] * b4.x;
            acc[i][1] += a[i] * b4.y;
            acc[i][2] += a[i] * b4.z;
            acc[i][3] += a[i] * b4.w;
        }
    }

    // Scatter stores into layout-specific scratch
#pragma unroll
    for (int i = 0; i < 4; i++) {
        int m = m0 + ty * 4 + i;
        int b = m >> 8, s = m & 255;
#pragma unroll
        for (int j = 0; j < 4; j++) {
            int f   = f0 + tx * 4 + j;
            float v = acc[i][j];
            int sec = f >> 7;        // 0:q 1:k 2:v 3:g
            int r   = f & 127;
            int h   = r >> 5, c = r & 31;
            if (sec == 0)      g_q[(((b * NHEADS + h) * SEQ) + s) * CHID + c] = v;
            else if (sec == 1) g_k[(((b * NHEADS + h) * SEQ) + s) * CHID + c] = v;
            else if (sec == 2) g_v[(((b * NHEADS + h) * CHID) + c) * SEQ + s] = v;  // transposed
            else               g_g[(b * SEQ + s) * HC + r] = v;
        }
    }
}

// ---------------------------------------------------------------------------
// Kernel 2: attention per (b, h, q-tile of 64).
//   S = (Q*scale) K^T  (+bias, +(mask-1)*1e9) -> softmax -> O = P V
// smem: Qs[64][33], Ks[256][33], VT[32][260], Ps[64][264]
// ---------------------------------------------------------------------------
#define A_QS_LD 33
#define A_KS_LD 33
#define A_VT_LD 260
#define A_PS_LD 264
#define A_SMEM  ((64 * A_QS_LD + 256 * A_KS_LD + 32 * A_VT_LD + 64 * A_PS_LD) * 4)

__global__ __launch_bounds__(256) void attn_kernel(
    const float* __restrict__ mask, const float* __restrict__ bias)
{
    extern __shared__ float sm[];
    float* Qs = sm;
    float* Ks = Qs + 64 * A_QS_LD;
    float* VT = Ks + 256 * A_KS_LD;
    float* Ps = VT + 32 * A_VT_LD;

    const int t  = threadIdx.x;
    const int q0 = blockIdx.x * 64;
    const int h  = blockIdx.y;
    const int b  = blockIdx.z;
    const float scale = 0.17677669529663687f;  // 1/sqrt(32)

    const size_t bh = (size_t)(b * NHEADS + h);
    const float* qg = g_q + bh * (SEQ * CHID) + (size_t)q0 * CHID;
    const float* kg = g_k + bh * (SEQ * CHID);
    const float* vg = g_v + bh * (SEQ * CHID);   // [c][s]

    // Load Q (scaled), 512 float4
#pragma unroll
    for (int i = 0; i < 2; i++) {
        int idx = i * 256 + t;
        int row = idx >> 3, c4 = idx & 7;
        float4 v = *(const float4*)(qg + row * CHID + c4 * 4);
        float* d = Qs + row * A_QS_LD + c4 * 4;
        d[0] = v.x * scale; d[1] = v.y * scale; d[2] = v.z * scale; d[3] = v.w * scale;
    }
    // Load K, 2048 float4
#pragma unroll
    for (int i = 0; i < 8; i++) {
        int idx = i * 256 + t;
        int row = idx >> 3, c4 = idx & 7;
        float4 v = *(const float4*)(kg + row * CHID + c4 * 4);
        float* d = Ks + row * A_KS_LD + c4 * 4;
        d[0] = v.x; d[1] = v.y; d[2] = v.z; d[3] = v.w;
    }
    // Load V transposed [32][256], 2048 float4 (already transposed in scratch)
#pragma unroll
    for (int i = 0; i < 8; i++) {
        int idx = i * 256 + t;
        int c = idx >> 6, s4 = idx & 63;
        float4 v = *(const float4*)(vg + c * SEQ + s4 * 4);
        *(float4*)(VT + c * A_VT_LD + s4 * 4) = v;
    }
    __syncthreads();

    const int tx = t & 15, ty = t >> 4;

    // Phase 1: scores.  Rows qi = ty*4+i, cols kj = tx + 16*j
    float acc[4][16];
#pragma unroll
    for (int i = 0; i < 4; i++)
#pragma unroll
        for (int j = 0; j < 16; j++) acc[i][j] = 0.0f;

#pragma unroll 4
    for (int d = 0; d < 32; d++) {
        float a[4];
#pragma unroll
        for (int i = 0; i < 4; i++) a[i] = Qs[(ty * 4 + i) * A_QS_LD + d];
#pragma unroll
        for (int j = 0; j < 16; j++) {
            float bk = Ks[(tx + 16 * j) * A_KS_LD + d];
#pragma unroll
            for (int i = 0; i < 4; i++) acc[i][j] += a[i] * bk;
        }
    }

    // mask term (same for all rows of this block)
    float mvals[16];
#pragma unroll
    for (int j = 0; j < 16; j++)
        mvals[j] = (mask[b * SEQ + tx + 16 * j] - 1.0f) * 1e9f;

    const float* bptr = bias + ((size_t)h * SEQ + q0) * SEQ;

    // softmax per row; each row is owned by a 16-lane half-warp (fixed ty)
#pragma unroll
    for (int i = 0; i < 4; i++) {
        const int qi = ty * 4 + i;
        float mx = -3.0e38f;
#pragma unroll
        for (int j = 0; j < 16; j++) {
            float x = acc[i][j] + bptr[qi * SEQ + tx + 16 * j] + mvals[j];
            acc[i][j] = x;
            mx = fmaxf(mx, x);
        }
#pragma unroll
        for (int d = 8; d >= 1; d >>= 1)
            mx = fmaxf(mx, __shfl_xor_sync(0xffffffffu, mx, d, 16));
        float sum = 0.0f;
#pragma unroll
        for (int j = 0; j < 16; j++) {
            float e = __expf(acc[i][j] - mx);
            acc[i][j] = e;
            sum += e;
        }
#pragma unroll
        for (int d = 8; d >= 1; d >>= 1)
            sum += __shfl_xor_sync(0xffffffffu, sum, d, 16);
        float inv = 1.0f / sum;
#pragma unroll
        for (int j = 0; j < 16; j++)
            Ps[qi * A_PS_LD + tx + 16 * j] = acc[i][j] * inv;
    }
    __syncthreads();

    // Phase 2: O[64][32] = P[64][256] @ V.  Thread: 4 rows x 2 channels (tx, tx+16)
    float o0[4] = {0, 0, 0, 0};
    float o1[4] = {0, 0, 0, 0};
#pragma unroll 4
    for (int k4 = 0; k4 < 64; k4++) {
        float4 vb0 = *(const float4*)(VT + tx * A_VT_LD + k4 * 4);
        float4 vb1 = *(const float4*)(VT + (tx + 16) * A_VT_LD + k4 * 4);
#pragma unroll
        for (int i = 0; i < 4; i++) {
            float4 p = *(const float4*)(Ps + (ty * 4 + i) * A_PS_LD + k4 * 4);
            o0[i] += p.x * vb0.x; o0[i] += p.y * vb0.y;
            o0[i] += p.z * vb0.z; o0[i] += p.w * vb0.w;
            o1[i] += p.x * vb1.x; o1[i] += p.y * vb1.y;
            o1[i] += p.z * vb1.z; o1[i] += p.w * vb1.w;
        }
    }
#pragma unroll
    for (int i = 0; i < 4; i++) {
        size_t base = ((size_t)(b * SEQ + q0 + ty * 4 + i)) * HC + h * CHID;
        g_o[base + tx]      = o0[i];
        g_o[base + tx + 16] = o1[i];
    }
}

// ---------------------------------------------------------------------------
// Kernel 3: gate + output projection + transposed add.
//   gated[m][f] = o[m][f] * sigmoid(g[m][f] + gbias[f])
//   proj[m][o]  = sum_f gated[m][f] * Wo[o][f] + bo[o]
//   out[s][b][o] = add[s][b][o] + proj[b*256+s][o]
// Block tile: 64 M x 128 N (full N).  Thread: 4 rows x 8 cols.
// ---------------------------------------------------------------------------
#define G3_AS_LD 132
#define G3_BS_LD 132
#define G3_SMEM  ((64 * G3_AS_LD + 128 * G3_BS_LD) * 4)

__device__ __forceinline__ float sigmoidf_(float x) {
    return 1.0f / (1.0f + __expf(-x));
}

__global__ __launch_bounds__(256) void outproj_kernel(
    const float* __restrict__ addt, const float* __restrict__ gbias,
    const float* __restrict__ Wo,   const float* __restrict__ bo,
    float* __restrict__ out)
{
    extern __shared__ float sm[];
    float* As = sm;                  // gated [64][132]
    float* Bs = sm + 64 * G3_AS_LD;  // WoT   [128][132]  (Bs[f][o])

    const int t  = threadIdx.x;
    const int m0 = blockIdx.x * 64;

    // Load gated A tile
#pragma unroll
    for (int i = 0; i < 8; i++) {
        int idx = i * 256 + t;
        int row = idx >> 5, c4 = idx & 31;
        size_t off = ((size_t)(m0 + row)) * HC + c4 * 4;
        float4 ov = *(const float4*)(g_o + off);
        float4 gv = *(const float4*)(g_g + off);
        float4 gb = *(const float4*)(gbias + c4 * 4);
        float4 r;
        r.x = ov.x * sigmoidf_(gv.x + gb.x);
        r.y = ov.y * sigmoidf_(gv.y + gb.y);
        r.z = ov.z * sigmoidf_(gv.z + gb.z);
        r.w = ov.w * sigmoidf_(gv.w + gb.w);
        *(float4*)(As + row * G3_AS_LD + c4 * 4) = r;
    }
    // Load Wo transposed: Bs[f][o] = Wo[o][f]
#pragma unroll
    for (int i = 0; i < 16; i++) {
        int idx = i * 256 + t;
        int o = idx >> 5, c4 = idx & 31;
        float4 v = *(const float4*)(Wo + (size_t)o * HC + c4 * 4);
        Bs[(c4 * 4 + 0) * G3_BS_LD + o] = v.x;
        Bs[(c4 * 4 + 1) * G3_BS_LD + o] = v.y;
        Bs[(c4 * 4 + 2) * G3_BS_LD + o] = v.z;
        Bs[(c4 * 4 + 3) * G3_BS_LD + o] = v.w;
    }
    __syncthreads();

    const int tx = t & 15, ty = t >> 4;
    float acc[4][8];
#pragma unroll
    for (int i = 0; i < 4; i++)
#pragma unroll
        for (int j = 0; j < 8; j++) acc[i][j] = 0.0f;

#pragma unroll 8
    for (int k = 0; k < 128; k++) {
        float a[4];
#pragma unroll
        for (int i = 0; i < 4; i++) a[i] = As[(ty * 4 + i) * G3_AS_LD + k];
        float4 b0 = *(const float4*)(Bs + k * G3_BS_LD + tx * 4);
        float4 b1 = *(const float4*)(Bs + k * G3_BS_LD + 64 + tx * 4);
#pragma unroll
        for (int i = 0; i < 4; i++) {
            acc[i][0] += a[i] * b0.x; acc[i][1] += a[i] * b0.y;
            acc[i][2] += a[i] * b0.z; acc[i][3] += a[i] * b0.w;
            acc[i][4] += a[i] * b1.x; acc[i][5] += a[i] * b1.y;
            acc[i][6] += a[i] * b1.z; acc[i][7] += a[i] * b1.w;
        }
    }

    float4 bo0 = *(const float4*)(bo + tx * 4);
    float4 bo1 = *(const float4*)(bo + 64 + tx * 4);
#pragma unroll
    for (int i = 0; i < 4; i++) {
        int m = m0 + ty * 4 + i;
        int b = m >> 8, s = m & 255;
        size_t obase = ((size_t)(s * SEQ + b)) * CQKV;  // out[s][b][:]
        float4 a0 = *(const float4*)(addt + obase + tx * 4);
        float4 a1 = *(const float4*)(addt + obase + 64 + tx * 4);
        float4 r0, r1;
        r0.x = acc[i][0] + bo0.x + a0.x; r0.y = acc[i][1] + bo0.y + a0.y;
        r0.z = acc[i][2] + bo0.z + a0.z; r0.w = acc[i][3] + bo0.w + a0.w;
        r1.x = acc[i][4] + bo1.x + a1.x; r1.y = acc[i][5] + bo1.y + a1.y;
        r1.z = acc[i][6] + bo1.z + a1.z; r1.w = acc[i][7] + bo1.w + a1.w;
        *(float4*)(out + obase + tx * 4) = r0;
        *(float4*)(out + obase + 64 + tx * 4) = r1;
    }
}

// ---------------------------------------------------------------------------
extern "C" void kernel_launch(void* const* d_in, const int* in_sizes, int n_in,
                              void* d_out, int out_size)
{
    const float* in_qkv = (const float*)d_in[0];
    const float* mask   = (const float*)d_in[1];
    const float* bias   = (const float*)d_in[2];
    const float* addt   = (const float*)d_in[3];
    const float* Wqkvg  = (const float*)d_in[4];
    const float* gbias  = (const float*)d_in[5];
    const float* Wo     = (const float*)d_in[6];
    const float* bo     = (const float*)d_in[7];
    float* out = (float*)d_out;

    cudaFuncSetAttribute(gemm_qkvg_kernel,
                         cudaFuncAttributeMaxDynamicSharedMemorySize, G1_SMEM);
    cudaFuncSetAttribute(attn_kernel,
                         cudaFuncAttributeMaxDynamicSharedMemorySize, A_SMEM);
    cudaFuncSetAttribute(outproj_kernel,
                         cudaFuncAttributeMaxDynamicSharedMemorySize, G3_SMEM);

    gemm_qkvg_kernel<<<dim3(1024, 8), 256, G1_SMEM>>>(in_qkv, Wqkvg);
    attn_kernel<<<dim3(4, NHEADS, BATCH), 256, A_SMEM>>>(mask, bias);
    outproj_kernel<<<dim3(1024), 256, G3_SMEM>>>(addt, gbias, Wo, bo, out);
}